// round 1
// baseline (speedup 1.0000x reference)
#include <cuda_runtime.h>
#include <math_constants.h>

// Problem constants
#define BB 16
#define DD 256
#define HH 32
#define WW 32
#define HW 1024           // H*W
#define NN 16384          // B*H*W
#define MM 2048

// GEMM tiling
#define TM 128
#define TN 128
#define TK 16
#define BS_STRIDE (TN + 4) // padded to keep float4 alignment + reduce conflicts

// Scratch (no device allocation allowed)
__device__ float    g_zsq[NN];
__device__ float    g_esq[MM];
__device__ unsigned g_colmin[MM];   // float bits; valid since distances >= 0

// ---------------------------------------------------------------------------
// init colmin to +inf (bits)
__global__ void init_colmin_kernel() {
    int i = blockIdx.x * blockDim.x + threadIdx.x;
    if (i < MM) g_colmin[i] = 0x7f800000u;
}

// ---------------------------------------------------------------------------
// e_sq[m] = sum_d e[m][d]^2 ; one warp per m
__global__ void esq_kernel(const float* __restrict__ e) {
    int warp = (blockIdx.x * blockDim.x + threadIdx.x) >> 5;
    int lane = threadIdx.x & 31;
    if (warp >= MM) return;
    const float* row = e + (size_t)warp * DD;
    float s = 0.f;
    #pragma unroll
    for (int i = 0; i < DD / 32; i++) {
        float v = row[lane + i * 32];
        s += v * v;
    }
    #pragma unroll
    for (int off = 16; off > 0; off >>= 1)
        s += __shfl_down_sync(0xffffffffu, s, off);
    if (lane == 0) g_esq[warp] = s;
}

// ---------------------------------------------------------------------------
// z_sq[n] = sum_d z[b][d][hw]^2 where n = b*HW + hw (coalesced across threads)
__global__ void zsq_kernel(const float* __restrict__ z) {
    int n = blockIdx.x * blockDim.x + threadIdx.x;
    if (n >= NN) return;
    int b  = n / HW;
    int hw = n % HW;
    const float* base = z + (size_t)b * DD * HW + hw;
    float s = 0.f;
    #pragma unroll 8
    for (int d = 0; d < DD; d++) {
        float v = base[(size_t)d * HW];
        s += v * v;
    }
    g_zsq[n] = s;
}

// ---------------------------------------------------------------------------
// Fused: distance tile (TM x TN) = zsq + esq - 2*z.e, clamped at 0,
// written to out; also blockwise column-min folded into g_colmin via atomicMin.
__global__ __launch_bounds__(256, 2)
void gemm_dist_kernel(const float* __restrict__ z, const float* __restrict__ e,
                      float* __restrict__ out) {
    __shared__ float As[TK][TM];
    __shared__ float Bs[TK][BS_STRIDE];
    __shared__ unsigned smin[TN];

    const int tid = threadIdx.x;           // 256 threads
    const int tx  = tid & 15;              // 16 col groups
    const int ty  = tid >> 4;              // 16 row groups

    const int n0 = blockIdx.x * TM;        // 128 n-tiles
    const int m0 = blockIdx.y * TN;        // 16  m-tiles

    // n-tile never crosses a batch boundary (128 | 1024)
    const int b   = n0 / HW;
    const int hw0 = n0 % HW;
    const float* zbase = z + (size_t)b * DD * HW + hw0;
    const float* ebase = e + (size_t)m0 * DD;

    float acc[8][8];
    #pragma unroll
    for (int i = 0; i < 8; i++)
        #pragma unroll
        for (int j = 0; j < 8; j++) acc[i][j] = 0.f;

    // A-load mapping: 256 threads -> (d = it*2 + tid/128, n = tid%128)
    const int a_n = tid & 127;
    const int a_d2 = tid >> 7;             // 0 or 1
    // B-load mapping: (d = tid%16, m = it*16 + tid/16)
    const int b_d = tid & 15;
    const int b_m = tid >> 4;

    for (int k0 = 0; k0 < DD; k0 += TK) {
        #pragma unroll
        for (int it = 0; it < 8; it++) {
            int d = it * 2 + a_d2;
            As[d][a_n] = zbase[(size_t)(k0 + d) * HW + a_n];
        }
        #pragma unroll
        for (int it = 0; it < 8; it++) {
            int m = it * 16 + b_m;
            Bs[b_d][m] = ebase[(size_t)m * DD + k0 + b_d];
        }
        __syncthreads();

        #pragma unroll
        for (int k = 0; k < TK; k++) {
            float4 a0 = *(const float4*)&As[k][ty * 8];
            float4 a1 = *(const float4*)&As[k][ty * 8 + 4];
            float4 b0 = *(const float4*)&Bs[k][tx * 8];
            float4 b1 = *(const float4*)&Bs[k][tx * 8 + 4];
            float av[8] = {a0.x, a0.y, a0.z, a0.w, a1.x, a1.y, a1.z, a1.w};
            float bv[8] = {b0.x, b0.y, b0.z, b0.w, b1.x, b1.y, b1.z, b1.w};
            #pragma unroll
            for (int i = 0; i < 8; i++)
                #pragma unroll
                for (int j = 0; j < 8; j++)
                    acc[i][j] = fmaf(av[i], bv[j], acc[i][j]);
        }
        __syncthreads();
    }

    // Epilogue: distance + store + column mins
    const int gn0 = n0 + ty * 8;
    const int gm0 = m0 + tx * 8;

    float zs[8], es[8];
    #pragma unroll
    for (int i = 0; i < 8; i++) zs[i] = g_zsq[gn0 + i];
    #pragma unroll
    for (int j = 0; j < 8; j++) es[j] = g_esq[gm0 + j];

    float cmin[8];
    #pragma unroll
    for (int j = 0; j < 8; j++) cmin[j] = CUDART_INF_F;

    #pragma unroll
    for (int i = 0; i < 8; i++) {
        float dv[8];
        #pragma unroll
        for (int j = 0; j < 8; j++) {
            float dist = fmaxf(zs[i] + es[j] - 2.0f * acc[i][j], 0.0f);
            dv[j] = dist;
            cmin[j] = fminf(cmin[j], dist);
        }
        float* orow = out + (size_t)(gn0 + i) * MM + gm0;
        *(float4*)&orow[0] = make_float4(dv[0], dv[1], dv[2], dv[3]);
        *(float4*)&orow[4] = make_float4(dv[4], dv[5], dv[6], dv[7]);
    }

    if (tid < TN) smin[tid] = 0x7f800000u;
    __syncthreads();
    #pragma unroll
    for (int j = 0; j < 8; j++)
        atomicMin(&smin[tx * 8 + j], __float_as_uint(cmin[j]));
    __syncthreads();
    if (tid < TN) atomicMin(&g_colmin[m0 + tid], smin[tid]);
}

// ---------------------------------------------------------------------------
// loss = mean over m of colmin[m]; single block
__global__ void loss_kernel(float* __restrict__ out_loss) {
    __shared__ float partial[256];
    int tid = threadIdx.x;
    float s = 0.f;
    for (int i = tid; i < MM; i += 256)
        s += __uint_as_float(g_colmin[i]);
    partial[tid] = s;
    __syncthreads();
    for (int off = 128; off > 0; off >>= 1) {
        if (tid < off) partial[tid] += partial[tid + off];
        __syncthreads();
    }
    if (tid == 0) out_loss[0] = partial[0] / (float)MM;
}

// ---------------------------------------------------------------------------
extern "C" void kernel_launch(void* const* d_in, const int* in_sizes, int n_in,
                              void* d_out, int out_size) {
    const float* z = (const float*)d_in[0];
    const float* e = (const float*)d_in[1];
    float* out = (float*)d_out;

    init_colmin_kernel<<<(MM + 255) / 256, 256>>>();
    esq_kernel<<<(MM * 32 + 255) / 256, 256>>>(e);
    zsq_kernel<<<(NN + 255) / 256, 256>>>(z);

    dim3 grid(NN / TM, MM / TN);   // (128, 16)
    gemm_dist_kernel<<<grid, 256>>>(z, e, out);

    if (out_size > (int)((size_t)NN * MM) || out_size < 0) {
        // out_size is int; NN*MM+1 = 33554433 fits. Loss goes after distance.
        loss_kernel<<<1, 256>>>(out + (size_t)NN * MM);
    }
}

// round 2
// speedup vs baseline: 1.0014x; 1.0014x over previous
#include <cuda_runtime.h>
#include <math_constants.h>

// Problem constants
#define BB 16
#define DD 256
#define HH 32
#define WW 32
#define HW 1024           // H*W
#define NN 16384          // B*H*W
#define MM 2048

// GEMM tiling
#define TM 128
#define TN 128
#define TK 16
#define BS_STRIDE (TN + 4) // padded to keep float4 alignment + reduce conflicts

// Scratch (no device allocation allowed)
__device__ float    g_zsq[NN];
__device__ float    g_esq[MM];
__device__ unsigned g_colmin[MM];   // float bits; valid since distances >= 0

// ---------------------------------------------------------------------------
// init colmin to +inf (bits)
__global__ void init_colmin_kernel() {
    int i = blockIdx.x * blockDim.x + threadIdx.x;
    if (i < MM) g_colmin[i] = 0x7f800000u;
}

// ---------------------------------------------------------------------------
// e_sq[m] = sum_d e[m][d]^2 ; one warp per m
__global__ void esq_kernel(const float* __restrict__ e) {
    int warp = (blockIdx.x * blockDim.x + threadIdx.x) >> 5;
    int lane = threadIdx.x & 31;
    if (warp >= MM) return;
    const float* row = e + (size_t)warp * DD;
    float s = 0.f;
    #pragma unroll
    for (int i = 0; i < DD / 32; i++) {
        float v = row[lane + i * 32];
        s += v * v;
    }
    #pragma unroll
    for (int off = 16; off > 0; off >>= 1)
        s += __shfl_down_sync(0xffffffffu, s, off);
    if (lane == 0) g_esq[warp] = s;
}

// ---------------------------------------------------------------------------
// z_sq[n] = sum_d z[b][d][hw]^2 where n = b*HW + hw (coalesced across threads)
__global__ void zsq_kernel(const float* __restrict__ z) {
    int n = blockIdx.x * blockDim.x + threadIdx.x;
    if (n >= NN) return;
    int b  = n / HW;
    int hw = n % HW;
    const float* base = z + (size_t)b * DD * HW + hw;
    float s = 0.f;
    #pragma unroll 8
    for (int d = 0; d < DD; d++) {
        float v = base[(size_t)d * HW];
        s += v * v;
    }
    g_zsq[n] = s;
}

// ---------------------------------------------------------------------------
// Fused: distance tile (TM x TN) = zsq + esq - 2*z.e, clamped at 0,
// written to out; also blockwise column-min folded into g_colmin via atomicMin.
__global__ __launch_bounds__(256, 2)
void gemm_dist_kernel(const float* __restrict__ z, const float* __restrict__ e,
                      float* __restrict__ out) {
    __shared__ float As[TK][TM];
    __shared__ float Bs[TK][BS_STRIDE];
    __shared__ unsigned smin[TN];

    const int tid = threadIdx.x;           // 256 threads
    const int tx  = tid & 15;              // 16 col groups
    const int ty  = tid >> 4;              // 16 row groups

    const int n0 = blockIdx.x * TM;        // 128 n-tiles
    const int m0 = blockIdx.y * TN;        // 16  m-tiles

    // n-tile never crosses a batch boundary (128 | 1024)
    const int b   = n0 / HW;
    const int hw0 = n0 % HW;
    const float* zbase = z + (size_t)b * DD * HW + hw0;
    const float* ebase = e + (size_t)m0 * DD;

    float acc[8][8];
    #pragma unroll
    for (int i = 0; i < 8; i++)
        #pragma unroll
        for (int j = 0; j < 8; j++) acc[i][j] = 0.f;

    // A-load mapping: 256 threads -> (d = it*2 + tid/128, n = tid%128)
    const int a_n = tid & 127;
    const int a_d2 = tid >> 7;             // 0 or 1
    // B-load mapping: (d = tid%16, m = it*16 + tid/16)
    const int b_d = tid & 15;
    const int b_m = tid >> 4;

    for (int k0 = 0; k0 < DD; k0 += TK) {
        #pragma unroll
        for (int it = 0; it < 8; it++) {
            int d = it * 2 + a_d2;
            As[d][a_n] = zbase[(size_t)(k0 + d) * HW + a_n];
        }
        #pragma unroll
        for (int it = 0; it < 8; it++) {
            int m = it * 16 + b_m;
            Bs[b_d][m] = ebase[(size_t)m * DD + k0 + b_d];
        }
        __syncthreads();

        #pragma unroll
        for (int k = 0; k < TK; k++) {
            float4 a0 = *(const float4*)&As[k][ty * 8];
            float4 a1 = *(const float4*)&As[k][ty * 8 + 4];
            float4 b0 = *(const float4*)&Bs[k][tx * 8];
            float4 b1 = *(const float4*)&Bs[k][tx * 8 + 4];
            float av[8] = {a0.x, a0.y, a0.z, a0.w, a1.x, a1.y, a1.z, a1.w};
            float bv[8] = {b0.x, b0.y, b0.z, b0.w, b1.x, b1.y, b1.z, b1.w};
            #pragma unroll
            for (int i = 0; i < 8; i++)
                #pragma unroll
                for (int j = 0; j < 8; j++)
                    acc[i][j] = fmaf(av[i], bv[j], acc[i][j]);
        }
        __syncthreads();
    }

    // Epilogue: distance + store + column mins
    const int gn0 = n0 + ty * 8;
    const int gm0 = m0 + tx * 8;

    float zs[8], es[8];
    #pragma unroll
    for (int i = 0; i < 8; i++) zs[i] = g_zsq[gn0 + i];
    #pragma unroll
    for (int j = 0; j < 8; j++) es[j] = g_esq[gm0 + j];

    float cmin[8];
    #pragma unroll
    for (int j = 0; j < 8; j++) cmin[j] = CUDART_INF_F;

    #pragma unroll
    for (int i = 0; i < 8; i++) {
        float dv[8];
        #pragma unroll
        for (int j = 0; j < 8; j++) {
            float dist = fmaxf(zs[i] + es[j] - 2.0f * acc[i][j], 0.0f);
            dv[j] = dist;
            cmin[j] = fminf(cmin[j], dist);
        }
        float* orow = out + (size_t)(gn0 + i) * MM + gm0;
        *(float4*)&orow[0] = make_float4(dv[0], dv[1], dv[2], dv[3]);
        *(float4*)&orow[4] = make_float4(dv[4], dv[5], dv[6], dv[7]);
    }

    if (tid < TN) smin[tid] = 0x7f800000u;
    __syncthreads();
    #pragma unroll
    for (int j = 0; j < 8; j++)
        atomicMin(&smin[tx * 8 + j], __float_as_uint(cmin[j]));
    __syncthreads();
    if (tid < TN) atomicMin(&g_colmin[m0 + tid], smin[tid]);
}

// ---------------------------------------------------------------------------
// loss = mean over m of colmin[m]; single block
__global__ void loss_kernel(float* __restrict__ out_loss) {
    __shared__ float partial[256];
    int tid = threadIdx.x;
    float s = 0.f;
    for (int i = tid; i < MM; i += 256)
        s += __uint_as_float(g_colmin[i]);
    partial[tid] = s;
    __syncthreads();
    for (int off = 128; off > 0; off >>= 1) {
        if (tid < off) partial[tid] += partial[tid + off];
        __syncthreads();
    }
    if (tid == 0) out_loss[0] = partial[0] / (float)MM;
}

// ---------------------------------------------------------------------------
extern "C" void kernel_launch(void* const* d_in, const int* in_sizes, int n_in,
                              void* d_out, int out_size) {
    const float* z = (const float*)d_in[0];
    const float* e = (const float*)d_in[1];
    float* out = (float*)d_out;

    init_colmin_kernel<<<(MM + 255) / 256, 256>>>();
    esq_kernel<<<(MM * 32 + 255) / 256, 256>>>(e);
    zsq_kernel<<<(NN + 255) / 256, 256>>>(z);

    dim3 grid(NN / TM, MM / TN);   // (128, 16)
    gemm_dist_kernel<<<grid, 256>>>(z, e, out);

    if (out_size > (int)((size_t)NN * MM) || out_size < 0) {
        // out_size is int; NN*MM+1 = 33554433 fits. Loss goes after distance.
        loss_kernel<<<1, 256>>>(out + (size_t)NN * MM);
    }
}

// round 4
// speedup vs baseline: 1.1911x; 1.1894x over previous
#include <cuda_runtime.h>
#include <mma.h>
#include <cstdint>
using namespace nvcuda;

#define NN 16384
#define MM 2048
#define DD 256

#define A_LD  264
#define B_LD  272
#define STG_LD 72

// dynamic SMEM layout (bytes)
#define SM_A    0                 // 128 x 264 f32 = 135168
#define SM_B    135168            // 2 x (16 x 272 f32 = 17408) = 34816
#define SM_STG  169984            // 128 x 72 f32 = 36864
#define SM_ZSQ  206848            // 256 f32
#define SM_ES   207872            // 256 f32
#define SM_SMIN 208896            // 256 u32
#define SMEM_TOTAL 209920

__device__ float    g_eT[DD * MM];     // e transposed [k][m], tf32-rounded
__device__ float    g_esq[MM];
__device__ unsigned g_colmin[MM];

// ---------------------------------------------------------------------------
__device__ __forceinline__ float to_tf32(float x) {
    float y; asm("cvt.rna.tf32.f32 %0, %1;" : "=f"(y) : "f"(x)); return y;
}
__device__ __forceinline__ uint32_t smem_u32(const void* p) {
    uint32_t a;
    asm("{ .reg .u64 t; cvta.to.shared.u64 t, %1; cvt.u32.u64 %0, t; }" : "=r"(a) : "l"(p));
    return a;
}
#define CP_ASYNC16(dst, src) \
    asm volatile("cp.async.cg.shared.global [%0], [%1], 16;" :: "r"(dst), "l"(src))
#define CP_COMMIT() asm volatile("cp.async.commit_group;" ::: "memory")
#define CP_WAIT(n)  asm volatile("cp.async.wait_group %0;" :: "n"(n) : "memory")

// ---------------------------------------------------------------------------
__global__ void init_colmin_kernel() {
    int i = blockIdx.x * blockDim.x + threadIdx.x;
    if (i < MM) g_colmin[i] = 0x7f800000u;
}

// e [m][k] -> g_eT [k][m], tf32-rounded. grid (64, 8), block (32, 8)
__global__ void prep_eT_kernel(const float* __restrict__ e) {
    __shared__ float t[32][33];
    int mb = blockIdx.x << 5, kb = blockIdx.y << 5;
    int tx = threadIdx.x, ty = threadIdx.y;
    #pragma unroll
    for (int i = 0; i < 32; i += 8)
        t[ty + i][tx] = e[(size_t)(mb + ty + i) * DD + kb + tx];
    __syncthreads();
    #pragma unroll
    for (int i = 0; i < 32; i += 8)
        g_eT[(size_t)(kb + ty + i) * MM + mb + tx] = to_tf32(t[tx][ty + i]);
}

__global__ void esq_kernel(const float* __restrict__ e) {
    int warp = (blockIdx.x * blockDim.x + threadIdx.x) >> 5;
    int lane = threadIdx.x & 31;
    if (warp >= MM) return;
    const float* row = e + (size_t)warp * DD;
    float s = 0.f;
    #pragma unroll
    for (int i = 0; i < DD / 32; i++) { float v = row[lane + i * 32]; s += v * v; }
    #pragma unroll
    for (int o = 16; o > 0; o >>= 1) s += __shfl_down_sync(0xffffffffu, s, o);
    if (lane == 0) g_esq[warp] = s;
}

// ---------------------------------------------------------------------------
// Persistent fused GEMM + distance + column-min. 128 CTAs x 256 threads.
__global__ void __launch_bounds__(256, 1)
gemm_dist_kernel(const float* __restrict__ z, float* __restrict__ out) {
    extern __shared__ char smem[];
    float* Asm  = (float*)(smem + SM_A);
    float* Bsm  = (float*)(smem + SM_B);
    float* stg  = (float*)(smem + SM_STG);
    float* zsq2 = (float*)(smem + SM_ZSQ);
    float* es   = (float*)(smem + SM_ES);
    unsigned* smin = (unsigned*)(smem + SM_SMIN);
    const uint32_t sbB = smem_u32(Bsm);

    const int tid = threadIdx.x;
    const int wid = tid >> 5;
    const int wy = wid & 1;          // n-dir (2)
    const int wx = wid >> 1;         // m-dir (4)
    const int n0 = blockIdx.x << 7;
    const float* zbase = z + (size_t)(n0 >> 10) * (DD * 1024) + (n0 & 1023);

    // ---- prologue: A = z-tile transposed [n][k] (tf32) + z_sq partials ----
    {
        float zacc = 0.f;
        const int an = tid & 127;
        const int dh = tid >> 7;
        #pragma unroll 4
        for (int it = 0; it < 128; it++) {
            int d = it * 2 + dh;
            float v = zbase[(size_t)d * 1024 + an];
            zacc += v * v;
            Asm[an * A_LD + d] = to_tf32(v);
        }
        zsq2[tid] = zacc;
        smin[tid] = 0x7f800000u;
    }
    __syncthreads();

    // ---- fragments ----
    wmma::fragment<wmma::accumulator, 16, 16, 8, float> cf[4][4];
    #pragma unroll
    for (int i = 0; i < 4; i++)
        #pragma unroll
        for (int c = 0; c < 4; c++) wmma::fill_fragment(cf[i][c], 0.f);

    // ---- B chunk loader: chunk u -> j = u>>4 (m-chunk 256), kc = u&15 (k 16) ----
    auto issueB = [&](int u) {
        int j = u >> 4, kc = u & 15, buf = u & 1;
        const float* src = g_eT + (size_t)(kc * 16) * MM + j * 256;
        uint32_t dst = sbB + buf * (16 * B_LD * 4);
        #pragma unroll
        for (int i = 0; i < 4; i++) {
            int op = tid + i * 256;          // 0..1023
            int r = op >> 6, s = op & 63;    // 16 rows x 64 x 16B
            CP_ASYNC16(dst + (uint32_t)(r * B_LD + s * 4) * 4,
                       src + (size_t)r * MM + s * 4);
        }
        CP_COMMIT();
    };

    issueB(0);
    issueB(1);

    for (int u = 0; u < 128; u++) {
        const int j = u >> 4, kc = u & 15, buf = u & 1;
        if (u < 127) { CP_WAIT(1); } else { CP_WAIT(0); }
        __syncthreads();

        const float* Bb = Bsm + buf * (16 * B_LD);
        #pragma unroll
        for (int ks = 0; ks < 2; ks++) {
            const int k0 = kc * 16 + ks * 8;
            wmma::fragment<wmma::matrix_a, 16, 16, 8, wmma::precision::tf32, wmma::row_major> af[4];
            wmma::fragment<wmma::matrix_b, 16, 16, 8, wmma::precision::tf32, wmma::row_major> bf[4];
            #pragma unroll
            for (int i = 0; i < 4; i++)
                wmma::load_matrix_sync(af[i], Asm + (wy * 64 + 16 * i) * A_LD + k0, A_LD);
            #pragma unroll
            for (int c = 0; c < 4; c++)
                wmma::load_matrix_sync(bf[c], Bb + (ks * 8) * B_LD + wx * 64 + 16 * c, B_LD);
            #pragma unroll
            for (int i = 0; i < 4; i++)
                #pragma unroll
                for (int c = 0; c < 4; c++)
                    wmma::mma_sync(cf[i][c], af[i], bf[c], cf[i][c]);
        }
        __syncthreads();
        if (u + 2 < 128) issueB(u + 2);

        if (kc == 15) {
            // ---------------- epilogue for m-chunk j (256 wide) ----------------
            es[tid] = g_esq[j * 256 + tid];

            #pragma unroll 1
            for (int q = 0; q < 4; q++) {
                __syncthreads();
                if (wx == q) {
                    #pragma unroll
                    for (int i = 0; i < 4; i++)
                        #pragma unroll
                        for (int c = 0; c < 4; c++)
                            wmma::store_matrix_sync(stg + (wy * 64 + 16 * i) * STG_LD + 16 * c,
                                                    cf[i][c], STG_LD, wmma::mem_row_major);
                }
                __syncthreads();

                // pass 1: distance + coalesced store (256B per row-pair of threads)
                {
                    const int r = tid >> 1;
                    const int c0 = (tid & 1) * 32;
                    const float zr = zsq2[r] + zsq2[r + 128];
                    float* op = out + (size_t)(n0 + r) * MM + j * 256 + q * 64 + c0;
                    #pragma unroll
                    for (int t = 0; t < 8; t++) {
                        float4 cv = *(const float4*)&stg[r * STG_LD + c0 + t * 4];
                        float4 dv;
                        dv.x = fmaxf(fmaf(-2.f, cv.x, zr + es[q * 64 + c0 + t * 4 + 0]), 0.f);
                        dv.y = fmaxf(fmaf(-2.f, cv.y, zr + es[q * 64 + c0 + t * 4 + 1]), 0.f);
                        dv.z = fmaxf(fmaf(-2.f, cv.z, zr + es[q * 64 + c0 + t * 4 + 2]), 0.f);
                        dv.w = fmaxf(fmaf(-2.f, cv.w, zr + es[q * 64 + c0 + t * 4 + 3]), 0.f);
                        *(float4*)(op + t * 4) = dv;
                    }
                }
                // pass 2: column mins (conflict-free column reads)
                {
                    const int col = tid & 63;
                    const int rs = tid >> 6;
                    const float ec = es[q * 64 + col];
                    float mn = __int_as_float(0x7f800000);
                    #pragma unroll
                    for (int t = 0; t < 32; t++) {
                        int rr = rs * 32 + t;
                        float c = stg[rr * STG_LD + col];
                        float d = fmaxf(fmaf(-2.f, c, (zsq2[rr] + zsq2[rr + 128]) + ec), 0.f);
                        mn = fminf(mn, d);
                    }
                    atomicMin(&smin[q * 64 + col], __float_as_uint(mn));
                }
            }
            __syncthreads();
            atomicMin(&g_colmin[j * 256 + tid], smin[tid]);
            smin[tid] = 0x7f800000u;

            #pragma unroll
            for (int i = 0; i < 4; i++)
                #pragma unroll
                for (int c = 0; c < 4; c++) wmma::fill_fragment(cf[i][c], 0.f);
        }
    }
}

// ---------------------------------------------------------------------------
__global__ void loss_kernel(float* __restrict__ out_loss) {
    __shared__ float partial[256];
    int tid = threadIdx.x;
    float s = 0.f;
    for (int i = tid; i < MM; i += 256) s += __uint_as_float(g_colmin[i]);
    partial[tid] = s;
    __syncthreads();
    for (int o = 128; o > 0; o >>= 1) {
        if (tid < o) partial[tid] += partial[tid + o];
        __syncthreads();
    }
    if (tid == 0) out_loss[0] = partial[0] / (float)MM;
}

// ---------------------------------------------------------------------------
extern "C" void kernel_launch(void* const* d_in, const int* in_sizes, int n_in,
                              void* d_out, int out_size) {
    const float* z = (const float*)d_in[0];
    const float* e = (const float*)d_in[1];
    float* out = (float*)d_out;

    cudaFuncSetAttribute(gemm_dist_kernel,
                         cudaFuncAttributeMaxDynamicSharedMemorySize, SMEM_TOTAL);

    init_colmin_kernel<<<(MM + 255) / 256, 256>>>();
    prep_eT_kernel<<<dim3(MM / 32, DD / 32), dim3(32, 8)>>>(e);
    esq_kernel<<<(MM * 32 + 255) / 256, 256>>>(e);

    gemm_dist_kernel<<<128, 256, SMEM_TOTAL>>>(z, out);

    loss_kernel<<<1, 256>>>(out + (size_t)NN * MM);
}